// round 8
// baseline (speedup 1.0000x reference)
#include <cuda_runtime.h>
#include <math.h>

// ---------------- problem constants ----------------
#define BATCH 64
#define TSEQ  256
#define INDIM 264
#define SU    512
#define NH    4
#define MSZ   32
#define NA    256
#define DB    256
#define COMBD 904
#define COMBP 1024
#define OUTD  1192
#define UPDD  424
#define HP    106

#define PARTW 1216
#define NPART 5           // 3 from gemmA (K 256 each) + 2 from gemmB (K 128 each)

// g_prm per-batch layout (floats)
#define PRM_E    0        // erase: e[4*m + h], 128
#define PRM_A    128      // add:   a[4*m + h], 128
#define PRM_K    256      // khat:  [h][m], 128
#define PRM_S    384      // shift: [h][3]
#define PRM_J    396      // jump:  [h][3]
#define PRM_JD   408
#define PRM_GAM  412
#define PRM_BETA 416
#define PRM_G    420
#define PRMSZ    432

// raw upd offsets per head
#define OFF_S     0
#define OFF_JD    3
#define OFF_J     4
#define OFF_GAM   7
#define OFF_ER    8
#define OFF_AD    40
#define OFF_K     72
#define OFF_BETA  104
#define OFF_G     105

#define EPSV 1e-12f

// ---------------- device-global scratch ----------------
__device__ float g_Wt[PARTW * COMBP];
__device__ float g_bias[PARTW];
__device__ float g_comb[BATCH * COMBP];
__device__ float g_part[NPART * BATCH * PARTW];
__device__ float g_prm[BATCH * PRMSZ];
__device__ float g_wt[BATCH * NH * NA];
__device__ float g_wtdyn[BATCH * NH * NA];
__device__ float g_mem[BATCH * MSZ * NA];

__device__ __forceinline__ float sigm(float x) { return 1.0f / (1.0f + __expf(-x)); }
__device__ __forceinline__ float splus(float x) {
    return fmaxf(x, 0.0f) + log1pf(__expf(-fabsf(x)));
}

// ---------------- weight repack ----------------
__global__ void pack_kernel(const float* __restrict__ Wo, const float* __restrict__ bo,
                            const float* __restrict__ Ws, const float* __restrict__ bs,
                            const float* __restrict__ Wu, const float* __restrict__ bu) {
    int idx = blockIdx.x * 256 + threadIdx.x;
    if (idx < PARTW * COMBP) {
        int j = idx >> 10;
        int k = idx & (COMBP - 1);
        float v = 0.0f;
        if (k < COMBD && j < OUTD) {
            if (j < DB)            v = Wo[k * DB + j];
            else if (j < DB + SU)  v = Ws[k * SU + (j - DB)];
            else                   v = Wu[k * UPDD + (j - DB - SU)];
        }
        g_Wt[idx] = v;
    }
    if (idx < PARTW) {
        g_bias[idx] = (idx >= OUTD) ? 0.0f
                    : (idx < DB) ? bo[idx]
                    : (idx < DB + SU) ? bs[idx - DB]
                    : bu[idx - DB - SU];
    }
}

// ---------------- init ----------------
__global__ void init_kernel(const float* __restrict__ x) {
    int b = blockIdx.x, tid = threadIdx.x;
    for (int i = tid; i < NH * NA; i += 256) {
        float v = ((i & (NA - 1)) == 0) ? 1.0f : 0.0f;
        g_wt[b * NH * NA + i]    = v;
        g_wtdyn[b * NH * NA + i] = v;
    }
    for (int i = tid; i < MSZ * NA; i += 256) g_mem[b * MSZ * NA + i] = 0.01f;
    for (int i = tid; i < COMBP; i += 256) {
        float v;
        if (i < INDIM)            v = x[((size_t)b * TSEQ + 0) * INDIM + i];
        else if (i < INDIM + SU)  v = 1.0f;
        else if (i < COMBD)       v = 0.01f;   // read_0 = mem0 col 0 = 0.01
        else                      v = 0.0f;    // zero pad (never rewritten)
        g_comb[b * COMBP + i] = v;
    }
}

// ---------------- shared gemm tile routine (64 rows x 32 cols, K = nsub*64) ----------------
__device__ __forceinline__ void gemm_tile(char* buf, int cb, int k0, int nsub, int pidx) {
    float (*cS)[68] = (float (*)[68])buf;
    float (*wS)[68] = (float (*)[68])(buf + 64 * 68 * sizeof(float));
    int tid = threadIdx.x;
    int j0 = cb * 32;
    int rq = tid >> 4, cp = tid & 15;
    int r0 = rq * 4;

    float4 cP[4], wP[2];
    {
        int kc = k0;
        #pragma unroll
        for (int s = 0; s < 4; s++) {
            int p = tid + s * 256;
            int r = p >> 4, k4 = p & 15;
            cP[s] = *(const float4*)&g_comb[r * COMBP + kc + 4 * k4];
        }
        #pragma unroll
        for (int s = 0; s < 2; s++) {
            int p = tid + s * 256;
            int jj = p >> 4, k4 = p & 15;
            wP[s] = *(const float4*)&g_Wt[(size_t)(j0 + jj) * COMBP + kc + 4 * k4];
        }
    }

    float a00 = 0.f, a01 = 0.f, a10 = 0.f, a11 = 0.f;
    float a20 = 0.f, a21 = 0.f, a30 = 0.f, a31 = 0.f;

    #pragma unroll 1
    for (int sub = 0; sub < nsub; sub++) {
        #pragma unroll
        for (int s = 0; s < 4; s++) {
            int p = tid + s * 256;
            int r = p >> 4, k4 = p & 15;
            *(float4*)&cS[r][4 * k4] = cP[s];
        }
        #pragma unroll
        for (int s = 0; s < 2; s++) {
            int p = tid + s * 256;
            int jj = p >> 4, k4 = p & 15;
            *(float4*)&wS[jj][4 * k4] = wP[s];
        }
        __syncthreads();

        if (sub < nsub - 1) {
            int kc = k0 + (sub + 1) * 64;
            #pragma unroll
            for (int s = 0; s < 4; s++) {
                int p = tid + s * 256;
                int r = p >> 4, k4 = p & 15;
                cP[s] = *(const float4*)&g_comb[r * COMBP + kc + 4 * k4];
            }
            #pragma unroll
            for (int s = 0; s < 2; s++) {
                int p = tid + s * 256;
                int jj = p >> 4, k4 = p & 15;
                wP[s] = *(const float4*)&g_Wt[(size_t)(j0 + jj) * COMBP + kc + 4 * k4];
            }
        }

        #pragma unroll 8
        for (int kk = 0; kk < 64; kk += 4) {
            float4 w0 = *(const float4*)&wS[cp][kk];
            float4 w1 = *(const float4*)&wS[cp + 16][kk];
            float4 q0 = *(const float4*)&cS[r0 + 0][kk];
            float4 q1 = *(const float4*)&cS[r0 + 1][kk];
            float4 q2 = *(const float4*)&cS[r0 + 2][kk];
            float4 q3 = *(const float4*)&cS[r0 + 3][kk];
            a00 = fmaf(q0.x, w0.x, a00); a00 = fmaf(q0.y, w0.y, a00);
            a00 = fmaf(q0.z, w0.z, a00); a00 = fmaf(q0.w, w0.w, a00);
            a01 = fmaf(q0.x, w1.x, a01); a01 = fmaf(q0.y, w1.y, a01);
            a01 = fmaf(q0.z, w1.z, a01); a01 = fmaf(q0.w, w1.w, a01);
            a10 = fmaf(q1.x, w0.x, a10); a10 = fmaf(q1.y, w0.y, a10);
            a10 = fmaf(q1.z, w0.z, a10); a10 = fmaf(q1.w, w0.w, a10);
            a11 = fmaf(q1.x, w1.x, a11); a11 = fmaf(q1.y, w1.y, a11);
            a11 = fmaf(q1.z, w1.z, a11); a11 = fmaf(q1.w, w1.w, a11);
            a20 = fmaf(q2.x, w0.x, a20); a20 = fmaf(q2.y, w0.y, a20);
            a20 = fmaf(q2.z, w0.z, a20); a20 = fmaf(q2.w, w0.w, a20);
            a21 = fmaf(q2.x, w1.x, a21); a21 = fmaf(q2.y, w1.y, a21);
            a21 = fmaf(q2.z, w1.z, a21); a21 = fmaf(q2.w, w1.w, a21);
            a30 = fmaf(q3.x, w0.x, a30); a30 = fmaf(q3.y, w0.y, a30);
            a30 = fmaf(q3.z, w0.z, a30); a30 = fmaf(q3.w, w0.w, a30);
            a31 = fmaf(q3.x, w1.x, a31); a31 = fmaf(q3.y, w1.y, a31);
            a31 = fmaf(q3.z, w1.z, a31); a31 = fmaf(q3.w, w1.w, a31);
        }
        __syncthreads();
    }

    float* pp = &g_part[(pidx * BATCH) * PARTW];
    pp[(r0 + 0) * PARTW + j0 + cp]      = a00;
    pp[(r0 + 0) * PARTW + j0 + cp + 16] = a01;
    pp[(r0 + 1) * PARTW + j0 + cp]      = a10;
    pp[(r0 + 1) * PARTW + j0 + cp + 16] = a11;
    pp[(r0 + 2) * PARTW + j0 + cp]      = a20;
    pp[(r0 + 2) * PARTW + j0 + cp + 16] = a21;
    pp[(r0 + 3) * PARTW + j0 + cp]      = a30;
    pp[(r0 + 3) * PARTW + j0 + cp + 16] = a31;
}

// ---------------- mega: cell_{t-1} (CTAs 0..255) || gemmA_t (CTAs 256..369) ----------------
// Cell CTA = (batch b, head h), 256 threads, thread owns address n.
__global__ void __launch_bounds__(256) mega_kernel(int t) {
    __shared__ __align__(16) char buf[40960];
    int tid = threadIdx.x;

    if (blockIdx.x >= 256) {
        // ---- gemmA: K in [0,768), 3 ksplits x 38 colblocks ----
        int a = blockIdx.x - 256;
        int cb = a / 3, ks = a - cb * 3;
        gemm_tile(buf, cb, ks * 256, 4, ks);
        return;
    }
    if (t == 0) return;   // no cell work before first combine

    // ---- cell for step t-1 ----
    float (*memS)[260] = (float (*)[260])buf;                 // 33280 B
    float* wtA  = (float*)(buf + 33280);                      // [4][256] 4096
    float* wgH  = (float*)(buf + 37376);                      // [256]
    float* wH   = (float*)(buf + 38400);                      // [256]
    float4* e4v = (float4*)(buf + 39424);                     // [32]
    float4* a4v = (float4*)(buf + 39936);                     // [32]
    float* pKs  = (float*)(buf + 40448);                      // [32]
    float* scl  = (float*)(buf + 40576);                      // [16]
    float* red  = (float*)(buf + 40640);                      // [16]

    int b = blockIdx.x >> 2, h = blockIdx.x & 3;
    int n = tid, lane = tid & 31, wid = tid >> 5;
    const float* prm = &g_prm[b * PRMSZ];

    float dynOld = g_wtdyn[(b * NH + h) * NA + n];

    // load mem (8 f4/thread), all-head wt (1 f4/thread), params
    #pragma unroll
    for (int s = 0; s < 8; s++) {
        int p = tid + s * 256;
        int m = p >> 6, c4 = p & 63;
        *(float4*)&memS[m][4 * c4] = ((const float4*)&g_mem[b * MSZ * NA])[p];
    }
    *(float4*)&wtA[4 * tid] = ((const float4*)&g_wt[b * NH * NA])[tid];
    if (tid < 32) {
        e4v[tid] = *(const float4*)&prm[PRM_E + 4 * tid];
        a4v[tid] = *(const float4*)&prm[PRM_A + 4 * tid];
        pKs[tid] = prm[PRM_K + h * 32 + tid];
    } else if (tid < 48) {
        int q = tid - 32;
        float v = 0.0f;
        if (q < 3)       v = prm[PRM_S + h * 3 + q];        // scl[0..2]
        else if (q < 6)  v = prm[PRM_J + h * 3 + (q - 3)];  // scl[3..5]
        else if (q == 6) v = prm[PRM_JD + h];
        else if (q == 7) v = prm[PRM_GAM + h];
        else if (q == 8) v = prm[PRM_BETA + h];
        else if (q == 9) v = prm[PRM_G + h];
        scl[q] = v;
    }
    __syncthreads();

    // memory write (erase, add) — identical in all 4 head CTAs; h==0 writes back
    #pragma unroll
    for (int s = 0; s < 8; s++) {
        int p = tid + s * 256;
        int m = p >> 6, c4 = p & 63;
        float4 mv = *(const float4*)&memS[m][4 * c4];
        float4 e4 = e4v[m], a4 = a4v[m];
        float4 w0 = *(const float4*)&wtA[0 * 256 + 4 * c4];
        float4 w1 = *(const float4*)&wtA[1 * 256 + 4 * c4];
        float4 w2 = *(const float4*)&wtA[2 * 256 + 4 * c4];
        float4 w3 = *(const float4*)&wtA[3 * 256 + 4 * c4];
        #pragma unroll
        for (int i = 0; i < 4; i++) {
            float vv = (&mv.x)[i];
            float q0 = (&w0.x)[i], q1 = (&w1.x)[i], q2 = (&w2.x)[i], q3 = (&w3.x)[i];
            float prod = (1.0f - e4.x * q0) * (1.0f - e4.y * q1)
                       * (1.0f - e4.z * q2) * (1.0f - e4.w * q3);
            float addv = a4.x * q0 + a4.y * q1 + a4.z * q2 + a4.w * q3;
            (&mv.x)[i] = vv * prod + addv;
        }
        *(float4*)&memS[m][4 * c4] = mv;
        if (h == 0) ((float4*)&g_mem[b * MSZ * NA])[p] = mv;
    }
    __syncthreads();

    // content score (own head): sc = beta * khat . memcol / (||memcol|| + eps)
    float beta = scl[8], g = scl[9];
    float ss = 0.0f, sc = 0.0f;
    #pragma unroll
    for (int m = 0; m < MSZ; m++) {
        float v = memS[m][n];
        ss = fmaf(v, v, ss);
        sc = fmaf(pKs[m], v, sc);
    }
    sc = sc * beta / (sqrtf(ss) + EPSV);

    // softmax without max-reduction: shift by beta (sc <= beta since cos <= 1)
    float e = __expf(sc - beta);
    float sv = e;
    #pragma unroll
    for (int o = 16; o; o >>= 1) sv += __shfl_xor_sync(0xffffffffu, sv, o);
    if (lane == 0) red[wid] = sv;
    __syncthreads();
    float tot = red[0] + red[1] + red[2] + red[3] + red[4] + red[5] + red[6] + red[7];
    float wc = e / tot;
    float wOld = wtA[h * 256 + n];
    wgH[n] = fmaf(g, wc - wOld, wOld);
    __syncthreads();

    // shift + sharpen
    float ws = scl[0] * wgH[(n + NA - 1) & (NA - 1)]
             + scl[1] * wgH[n]
             + scl[2] * wgH[(n + 1) & (NA - 1)];
    ws = __expf(scl[7] * __logf(ws + EPSV));
    float sv2 = ws;
    #pragma unroll
    for (int o = 16; o; o >>= 1) sv2 += __shfl_xor_sync(0xffffffffu, sv2, o);
    if (lane == 0) red[8 + wid] = sv2;
    __syncthreads();
    float tot2 = red[8] + red[9] + red[10] + red[11] + red[12] + red[13] + red[14] + red[15];
    ws /= tot2;

    // snapshot + jump
    float jd = scl[6];
    float dynNew = fmaf(jd, ws - dynOld, dynOld);
    g_wtdyn[(b * NH + h) * NA + n] = dynNew;
    float wnew = scl[3] * ws + scl[4] * dynNew + ((n == 0) ? scl[5] : 0.0f);
    g_wt[(b * NH + h) * NA + n] = wnew;
    wH[n] = wnew;
    __syncthreads();

    // read[h][m] = sum_n wH[n] * memS[m][n]  -> comb read segment
    {
        int m = tid >> 3, s = tid & 7;
        float acc = 0.0f;
        #pragma unroll
        for (int i = 0; i < 32; i++) {
            int nn = s * 32 + ((i + m + 4 * s) & 31);   // conflict-free rotation
            acc = fmaf(wH[nn], memS[m][nn], acc);
        }
        acc += __shfl_down_sync(0xffffffffu, acc, 4, 8);
        acc += __shfl_down_sync(0xffffffffu, acc, 2, 8);
        acc += __shfl_down_sync(0xffffffffu, acc, 1, 8);
        if (s == 0) g_comb[b * COMBP + INDIM + SU + h * 32 + m] = acc;
    }
}

// ---------------- gemmB: K in [768,1024), 2 ksplits of 128 ----------------
__global__ void __launch_bounds__(256) gemmB_kernel() {
    __shared__ __align__(16) char buf[26112];
    gemm_tile(buf, blockIdx.x, 768 + blockIdx.y * 128, 2, 3 + blockIdx.y);
}

// ---------------- combine: sum 5 parts + bias; route; parse params ----------------
__global__ void __launch_bounds__(256) combine_kernel(const float* __restrict__ x,
                                                      float* __restrict__ dout, int t) {
    __shared__ float upS[448];
    int b = blockIdx.x, tid = threadIdx.x;

    #pragma unroll 2
    for (int i4 = tid; i4 < 304; i4 += 256) {
        float4 acc = ((const float4*)g_bias)[i4];
        #pragma unroll
        for (int p = 0; p < NPART; p++) {
            float4 v = ((const float4*)&g_part[(p * BATCH + b) * PARTW])[i4];
            acc.x += v.x; acc.y += v.y; acc.z += v.z; acc.w += v.w;
        }
        int j = 4 * i4;
        if (j < DB) {
            float4 o = make_float4(sigm(acc.x), sigm(acc.y), sigm(acc.z), sigm(acc.w));
            *(float4*)&dout[((size_t)b * TSEQ + t) * DB + j] = o;
        } else if (j < DB + SU) {
            float4 o = make_float4(sigm(acc.x), sigm(acc.y), sigm(acc.z), sigm(acc.w));
            *(float4*)&g_comb[b * COMBP + j + 8] = o;   // state -> comb[264 + (j-256)]
        } else {
            *(float4*)&upS[j - 768] = acc;               // raw interface params
        }
    }
    __syncthreads();

    // parse params -> g_prm[b]
    float* prm = &g_prm[b * PRMSZ];
    if (tid < NH * 32) {
        int hh = tid >> 5, m = tid & 31;
        const float* up = &upS[hh * HP];
        prm[PRM_E + 4 * m + hh] = sigm(up[OFF_ER + m]);
        prm[PRM_A + 4 * m + hh] = up[OFF_AD + m];
        float kt = tanhf(up[OFF_K + m]);
        float ssk = kt * kt;
        #pragma unroll
        for (int o = 16; o; o >>= 1) ssk += __shfl_xor_sync(0xffffffffu, ssk, o);
        prm[PRM_K + hh * 32 + m] = kt / (sqrtf(ssk) + EPSV);
        if (m == 0) {
            float s0 = splus(up[OFF_S + 0]), s1 = splus(up[OFF_S + 1]), s2 = splus(up[OFF_S + 2]);
            float mx = fmaxf(s0, fmaxf(s1, s2));
            float e0 = __expf(s0 - mx), e1 = __expf(s1 - mx), e2 = __expf(s2 - mx);
            float inv = 1.0f / (e0 + e1 + e2);
            prm[PRM_S + hh * 3 + 0] = e0 * inv;
            prm[PRM_S + hh * 3 + 1] = e1 * inv;
            prm[PRM_S + hh * 3 + 2] = e2 * inv;
            float j0r = up[OFF_J + 0], j1r = up[OFF_J + 1], j2r = up[OFF_J + 2];
            float jm = fmaxf(j0r, fmaxf(j1r, j2r));
            float f0 = __expf(j0r - jm), f1 = __expf(j1r - jm), f2 = __expf(j2r - jm);
            float jinv = 1.0f / (f0 + f1 + f2);
            prm[PRM_J + hh * 3 + 0] = f0 * jinv;
            prm[PRM_J + hh * 3 + 1] = f1 * jinv;
            prm[PRM_J + hh * 3 + 2] = f2 * jinv;
            prm[PRM_JD + hh]   = sigm(up[OFF_JD]);
            prm[PRM_GAM + hh]  = 1.0f + splus(up[OFF_GAM]);
            prm[PRM_BETA + hh] = splus(up[OFF_BETA]);
            prm[PRM_G + hh]    = sigm(up[OFF_G]);
        }
    }

    // x_{t+1} -> comb
    if (t < TSEQ - 1 && tid < 66) {
        float4 xv = *(const float4*)&x[((size_t)b * TSEQ + (t + 1)) * INDIM + 4 * tid];
        *(float4*)&g_comb[b * COMBP + 4 * tid] = xv;
    }
}

// ---------------- host ----------------
extern "C" void kernel_launch(void* const* d_in, const int* in_sizes, int n_in,
                              void* d_out, int out_size) {
    const float* x  = (const float*)d_in[0];
    const float* Wo = (const float*)d_in[1];
    const float* bo = (const float*)d_in[2];
    const float* Ws = (const float*)d_in[3];
    const float* bs = (const float*)d_in[4];
    const float* Wu = (const float*)d_in[5];
    const float* bu = (const float*)d_in[6];
    float* out = (float*)d_out;

    pack_kernel<<<(PARTW * COMBP + 255) / 256, 256>>>(Wo, bo, Ws, bs, Wu, bu);
    init_kernel<<<BATCH, 256>>>(x);
    for (int t = 0; t < TSEQ; t++) {
        mega_kernel<<<256 + 114, 256>>>(t);          // cell_{t-1} || gemmA_t
        gemmB_kernel<<<dim3(38, 2), 256>>>();        // needs read_t from cell
        combine_kernel<<<BATCH, 256>>>(x, out, t);   // dout_t, state_{t+1}, params_t
    }
}

// round 9
// speedup vs baseline: 1.5256x; 1.5256x over previous
#include <cuda_runtime.h>
#include <math.h>

// ---------------- problem constants ----------------
#define BATCH 64
#define TSEQ  256
#define INDIM 264
#define SU    512
#define NH    4
#define MSZ   32
#define NA    256
#define DB    256
#define COMBD 904
#define COMBP 1024
#define OUTD  1192
#define UPDD  424
#define HP    106

#define KSPLIT 4
#define KCH    256
#define KSUB   64
#define NCB    38
#define PARTW  1216

// raw upd offsets per head
#define OFF_S     0
#define OFF_JD    3
#define OFF_J     4
#define OFF_GAM   7
#define OFF_ER    8
#define OFF_AD    40
#define OFF_K     72
#define OFF_BETA  104
#define OFF_G     105

#define EPSV 1e-12f

#define MEMSZ (BATCH * MSZ * NA)
#define WTSZ  (BATCH * NH * NA)

// ---------------- device-global scratch ----------------
__device__ float g_Wt[PARTW * COMBP];
__device__ float g_bias[PARTW];
__device__ float g_comb[BATCH * COMBP];
__device__ float g_part[KSPLIT * BATCH * PARTW];
__device__ float g_wt[2 * WTSZ];        // double-buffered by step parity
__device__ float g_wtdyn[WTSZ];
__device__ float g_mem[2 * MEMSZ];      // double-buffered by step parity

__device__ __forceinline__ float sigm(float x) { return 1.0f / (1.0f + __expf(-x)); }
__device__ __forceinline__ float splus(float x) {
    return fmaxf(x, 0.0f) + log1pf(__expf(-fabsf(x)));
}

// ---------------- weight repack ----------------
__global__ void pack_kernel(const float* __restrict__ Wo, const float* __restrict__ bo,
                            const float* __restrict__ Ws, const float* __restrict__ bs,
                            const float* __restrict__ Wu, const float* __restrict__ bu) {
    int idx = blockIdx.x * 256 + threadIdx.x;
    if (idx < PARTW * COMBP) {
        int j = idx >> 10;
        int k = idx & (COMBP - 1);
        float v = 0.0f;
        if (k < COMBD && j < OUTD) {
            if (j < DB)            v = Wo[k * DB + j];
            else if (j < DB + SU)  v = Ws[k * SU + (j - DB)];
            else                   v = Wu[k * UPDD + (j - DB - SU)];
        }
        g_Wt[idx] = v;
    }
    if (idx < PARTW) {
        g_bias[idx] = (idx >= OUTD) ? 0.0f
                    : (idx < DB) ? bo[idx]
                    : (idx < DB + SU) ? bs[idx - DB]
                    : bu[idx - DB - SU];
    }
}

// ---------------- init: reset carry (parity-0 buffers) + comb_0 ----------------
__global__ void init_kernel(const float* __restrict__ x) {
    int b = blockIdx.x, tid = threadIdx.x;
    for (int i = tid; i < NH * NA; i += 256) {
        float v = ((i & (NA - 1)) == 0) ? 1.0f : 0.0f;
        g_wt[b * NH * NA + i]    = v;
        g_wtdyn[b * NH * NA + i] = v;
    }
    for (int i = tid; i < MSZ * NA; i += 256) g_mem[b * MSZ * NA + i] = 0.01f;
    for (int i = tid; i < COMBP; i += 256) {
        float v;
        if (i < INDIM)            v = x[((size_t)b * TSEQ + 0) * INDIM + i];
        else if (i < INDIM + SU)  v = 1.0f;
        else if (i < COMBD)       v = 0.01f;
        else                      v = 0.0f;
        g_comb[b * COMBP + i] = v;
    }
}

// ---------------- GEMM: partial[ks][row][col]; grid (38,4), 256 thr ----------------
__global__ void __launch_bounds__(256) gemm_kernel() {
    __shared__ float cS[64][KSUB + 4];
    __shared__ float wS[32][KSUB + 4];

    int tid = threadIdx.x;
    int cb = blockIdx.x, ks = blockIdx.y;
    int j0 = cb * 32;
    int k0 = ks * KCH;
    int rq = tid >> 4, cp = tid & 15;
    int r0 = rq * 4;

    float acc00 = 0.f, acc01 = 0.f, acc10 = 0.f, acc11 = 0.f;
    float acc20 = 0.f, acc21 = 0.f, acc30 = 0.f, acc31 = 0.f;

    float4 cP[4], wP[2];
    {
        int kc = k0;
        #pragma unroll
        for (int s = 0; s < 4; s++) {
            int p = tid + s * 256;
            int r = p >> 4, k4 = p & 15;
            cP[s] = *(const float4*)&g_comb[r * COMBP + kc + 4 * k4];
        }
        #pragma unroll
        for (int s = 0; s < 2; s++) {
            int p = tid + s * 256;
            int jj = p >> 4, k4 = p & 15;
            wP[s] = *(const float4*)&g_Wt[(size_t)(j0 + jj) * COMBP + kc + 4 * k4];
        }
    }

    #pragma unroll 1
    for (int sub = 0; sub < KCH / KSUB; sub++) {
        #pragma unroll
        for (int s = 0; s < 4; s++) {
            int p = tid + s * 256;
            int r = p >> 4, k4 = p & 15;
            *(float4*)&cS[r][4 * k4] = cP[s];
        }
        #pragma unroll
        for (int s = 0; s < 2; s++) {
            int p = tid + s * 256;
            int jj = p >> 4, k4 = p & 15;
            *(float4*)&wS[jj][4 * k4] = wP[s];
        }
        __syncthreads();

        if (sub < KCH / KSUB - 1) {
            int kc = k0 + (sub + 1) * KSUB;
            #pragma unroll
            for (int s = 0; s < 4; s++) {
                int p = tid + s * 256;
                int r = p >> 4, k4 = p & 15;
                cP[s] = *(const float4*)&g_comb[r * COMBP + kc + 4 * k4];
            }
            #pragma unroll
            for (int s = 0; s < 2; s++) {
                int p = tid + s * 256;
                int jj = p >> 4, k4 = p & 15;
                wP[s] = *(const float4*)&g_Wt[(size_t)(j0 + jj) * COMBP + kc + 4 * k4];
            }
        }

        #pragma unroll 8
        for (int kk = 0; kk < KSUB; kk += 4) {
            float4 w0 = *(const float4*)&wS[cp][kk];
            float4 w1 = *(const float4*)&wS[cp + 16][kk];
            float4 q0 = *(const float4*)&cS[r0 + 0][kk];
            float4 q1 = *(const float4*)&cS[r0 + 1][kk];
            float4 q2 = *(const float4*)&cS[r0 + 2][kk];
            float4 q3 = *(const float4*)&cS[r0 + 3][kk];
            acc00 = fmaf(q0.x, w0.x, acc00); acc00 = fmaf(q0.y, w0.y, acc00);
            acc00 = fmaf(q0.z, w0.z, acc00); acc00 = fmaf(q0.w, w0.w, acc00);
            acc01 = fmaf(q0.x, w1.x, acc01); acc01 = fmaf(q0.y, w1.y, acc01);
            acc01 = fmaf(q0.z, w1.z, acc01); acc01 = fmaf(q0.w, w1.w, acc01);
            acc10 = fmaf(q1.x, w0.x, acc10); acc10 = fmaf(q1.y, w0.y, acc10);
            acc10 = fmaf(q1.z, w0.z, acc10); acc10 = fmaf(q1.w, w0.w, acc10);
            acc11 = fmaf(q1.x, w1.x, acc11); acc11 = fmaf(q1.y, w1.y, acc11);
            acc11 = fmaf(q1.z, w1.z, acc11); acc11 = fmaf(q1.w, w1.w, acc11);
            acc20 = fmaf(q2.x, w0.x, acc20); acc20 = fmaf(q2.y, w0.y, acc20);
            acc20 = fmaf(q2.z, w0.z, acc20); acc20 = fmaf(q2.w, w0.w, acc20);
            acc21 = fmaf(q2.x, w1.x, acc21); acc21 = fmaf(q2.y, w1.y, acc21);
            acc21 = fmaf(q2.z, w1.z, acc21); acc21 = fmaf(q2.w, w1.w, acc21);
            acc30 = fmaf(q3.x, w0.x, acc30); acc30 = fmaf(q3.y, w0.y, acc30);
            acc30 = fmaf(q3.z, w0.z, acc30); acc30 = fmaf(q3.w, w0.w, acc30);
            acc31 = fmaf(q3.x, w1.x, acc31); acc31 = fmaf(q3.y, w1.y, acc31);
            acc31 = fmaf(q3.z, w1.z, acc31); acc31 = fmaf(q3.w, w1.w, acc31);
        }
        __syncthreads();
    }

    float* pp = &g_part[(ks * BATCH) * PARTW];
    pp[(r0 + 0) * PARTW + j0 + cp]      = acc00;
    pp[(r0 + 0) * PARTW + j0 + cp + 16] = acc01;
    pp[(r0 + 1) * PARTW + j0 + cp]      = acc10;
    pp[(r0 + 1) * PARTW + j0 + cp + 16] = acc11;
    pp[(r0 + 2) * PARTW + j0 + cp]      = acc20;
    pp[(r0 + 2) * PARTW + j0 + cp + 16] = acc21;
    pp[(r0 + 3) * PARTW + j0 + cp]      = acc30;
    pp[(r0 + 3) * PARTW + j0 + cp + 16] = acc31;
}

// ---------------- update: combine + DWM cell; grid=256 (b,h), 256 thr ----------------
__global__ void __launch_bounds__(256) update_kernel(const float* __restrict__ x,
                                                     float* __restrict__ dout, int t) {
    __shared__ float memS[MSZ][260];    // conflict-free row & column access
    __shared__ float wtA[NH * NA];
    __shared__ float wgH[NA];
    __shared__ float wH[NA];
    __shared__ float4 e4v[MSZ], a4v[MSZ];
    __shared__ float pKs[MSZ];
    __shared__ float scl[16];
    __shared__ float red[16];
    __shared__ float upS[HP + 2];

    int b = blockIdx.x >> 2, h = blockIdx.x & 3;
    int tid = threadIdx.x;
    int n = tid, lane = tid & 31, wid = tid >> 5;
    int par = t & 1;

    const float* P0 = &g_part[(0 * BATCH + b) * PARTW];
    const float* P1 = &g_part[(1 * BATCH + b) * PARTW];
    const float* P2 = &g_part[(2 * BATCH + b) * PARTW];
    const float* P3 = &g_part[(3 * BATCH + b) * PARTW];

    float dynOld = g_wtdyn[(b * NH + h) * NA + n];

    // ---- load mem (8 f4/thread) and all-head wt from parity buffers ----
    const float4* memIn = (const float4*)(g_mem + par * MEMSZ + b * MSZ * NA);
    #pragma unroll
    for (int s = 0; s < 8; s++) {
        int p = tid + s * 256;
        int m = p >> 6, c4 = p & 63;
        *(float4*)&memS[m][4 * c4] = memIn[p];
    }
    *(float4*)&wtA[4 * tid] = ((const float4*)(g_wt + par * WTSZ + b * NH * NA))[tid];

    // ---- combine partials for this CTA's slices ----
    // out cols [64h, 64h+64)
    if (tid < 64) {
        int j = 64 * h + tid;
        float v = P0[j] + P1[j] + P2[j] + P3[j] + g_bias[j];
        dout[((size_t)b * TSEQ + t) * DB + j] = sigm(v);
    }
    // state cols [256+128h, 256+128h+128) -> comb
    if (tid < 128) {
        int j = 256 + 128 * h + tid;
        float v = P0[j] + P1[j] + P2[j] + P3[j] + g_bias[j];
        g_comb[b * COMBP + j + 8] = sigm(v);   // comb idx = INDIM + (j-256)
    }
    // own-head raw params
    if (tid < HP) {
        int j = 768 + HP * h + tid;
        upS[tid] = P0[j] + P1[j] + P2[j] + P3[j] + g_bias[j];
    }
    // erase/add for ALL heads (needed by the shared memory write)
    {
        int hp = tid >> 6, idx = tid & 63;
        int j = 768 + HP * hp + OFF_ER + idx;
        float v = P0[j] + P1[j] + P2[j] + P3[j] + g_bias[j];
        if (idx < 32) ((float*)&e4v[idx])[hp] = sigm(v);
        else          ((float*)&a4v[idx - 32])[hp] = v;
    }
    __syncthreads();   // S1

    // ---- parse own-head params ----
    if (tid < 32) {
        float kt = tanhf(upS[OFF_K + tid]);
        float ssk = kt * kt;
        #pragma unroll
        for (int o = 16; o; o >>= 1) ssk += __shfl_xor_sync(0xffffffffu, ssk, o);
        pKs[tid] = kt / (sqrtf(ssk) + EPSV);
        if (tid == 0) {
            float s0 = splus(upS[OFF_S + 0]), s1 = splus(upS[OFF_S + 1]), s2 = splus(upS[OFF_S + 2]);
            float mx = fmaxf(s0, fmaxf(s1, s2));
            float e0 = __expf(s0 - mx), e1 = __expf(s1 - mx), e2 = __expf(s2 - mx);
            float inv = 1.0f / (e0 + e1 + e2);
            scl[0] = e0 * inv; scl[1] = e1 * inv; scl[2] = e2 * inv;
            float j0r = upS[OFF_J + 0], j1r = upS[OFF_J + 1], j2r = upS[OFF_J + 2];
            float jm = fmaxf(j0r, fmaxf(j1r, j2r));
            float f0 = __expf(j0r - jm), f1 = __expf(j1r - jm), f2 = __expf(j2r - jm);
            float jinv = 1.0f / (f0 + f1 + f2);
            scl[3] = f0 * jinv; scl[4] = f1 * jinv; scl[5] = f2 * jinv;
            scl[6] = sigm(upS[OFF_JD]);
            scl[7] = 1.0f + splus(upS[OFF_GAM]);
            scl[8] = splus(upS[OFF_BETA]);
            scl[9] = sigm(upS[OFF_G]);
        }
    }

    // ---- memory write (erase, add) — identical in all 4 head-CTAs; h==0 persists ----
    float4* memOut = (float4*)(g_mem + (par ^ 1) * MEMSZ + b * MSZ * NA);
    #pragma unroll
    for (int s = 0; s < 8; s++) {
        int p = tid + s * 256;
        int m = p >> 6, c4 = p & 63;
        float4 mv = *(const float4*)&memS[m][4 * c4];
        float4 e4 = e4v[m], a4 = a4v[m];
        float4 w0 = *(const float4*)&wtA[0 * 256 + 4 * c4];
        float4 w1 = *(const float4*)&wtA[1 * 256 + 4 * c4];
        float4 w2 = *(const float4*)&wtA[2 * 256 + 4 * c4];
        float4 w3 = *(const float4*)&wtA[3 * 256 + 4 * c4];
        #pragma unroll
        for (int i = 0; i < 4; i++) {
            float vv = (&mv.x)[i];
            float q0 = (&w0.x)[i], q1 = (&w1.x)[i], q2 = (&w2.x)[i], q3 = (&w3.x)[i];
            float prod = (1.0f - e4.x * q0) * (1.0f - e4.y * q1)
                       * (1.0f - e4.z * q2) * (1.0f - e4.w * q3);
            float addv = a4.x * q0 + a4.y * q1 + a4.z * q2 + a4.w * q3;
            (&mv.x)[i] = vv * prod + addv;
        }
        *(float4*)&memS[m][4 * c4] = mv;
        if (h == 0) memOut[p] = mv;
    }
    __syncthreads();   // S2

    // ---- content score: sc = beta * khat . memcol / ||memcol|| ----
    float beta = scl[8], g = scl[9];
    float ss = 0.0f, sc = 0.0f;
    #pragma unroll
    for (int m = 0; m < MSZ; m++) {
        float v = memS[m][n];
        ss = fmaf(v, v, ss);
        sc = fmaf(pKs[m], v, sc);
    }
    sc = sc * beta / (sqrtf(ss) + EPSV);

    // softmax shifted by beta (valid upper bound since cos <= 1)
    float e = __expf(sc - beta);
    float sv = e;
    #pragma unroll
    for (int o = 16; o; o >>= 1) sv += __shfl_xor_sync(0xffffffffu, sv, o);
    if (lane == 0) red[wid] = sv;
    __syncthreads();   // S3
    float tot = red[0] + red[1] + red[2] + red[3] + red[4] + red[5] + red[6] + red[7];
    float wc = e / tot;
    float wOld = wtA[h * 256 + n];
    wgH[n] = fmaf(g, wc - wOld, wOld);
    __syncthreads();   // S4

    // ---- shift + sharpen ----
    float ws = scl[0] * wgH[(n + NA - 1) & (NA - 1)]
             + scl[1] * wgH[n]
             + scl[2] * wgH[(n + 1) & (NA - 1)];
    ws = __expf(scl[7] * __logf(ws + EPSV));
    float sv2 = ws;
    #pragma unroll
    for (int o = 16; o; o >>= 1) sv2 += __shfl_xor_sync(0xffffffffu, sv2, o);
    if (lane == 0) red[8 + wid] = sv2;
    __syncthreads();   // S5
    float tot2 = red[8] + red[9] + red[10] + red[11] + red[12] + red[13] + red[14] + red[15];
    ws /= tot2;

    // ---- snapshot + jump ----
    float jd = scl[6];
    float dynNew = fmaf(jd, ws - dynOld, dynOld);
    g_wtdyn[(b * NH + h) * NA + n] = dynNew;
    float wnew = scl[3] * ws + scl[4] * dynNew + ((n == 0) ? scl[5] : 0.0f);
    g_wt[(par ^ 1) * WTSZ + (b * NH + h) * NA + n] = wnew;
    wH[n] = wnew;
    __syncthreads();   // S6

    // ---- read[h][m] = sum_n wH[n] * memS[m][n] -> comb read segment ----
    {
        int m = tid >> 3, s = tid & 7;
        float acc = 0.0f;
        #pragma unroll
        for (int i = 0; i < 32; i++) {
            int nn = s * 32 + ((i + m + 4 * s) & 31);
            acc = fmaf(wH[nn], memS[m][nn], acc);
        }
        acc += __shfl_down_sync(0xffffffffu, acc, 4, 8);
        acc += __shfl_down_sync(0xffffffffu, acc, 2, 8);
        acc += __shfl_down_sync(0xffffffffu, acc, 1, 8);
        if (s == 0) g_comb[b * COMBP + INDIM + SU + h * 32 + m] = acc;
    }

    // ---- x_{t+1} -> comb (h==0 only) ----
    if (h == 0 && tid < 66) {
        float4 xv = *(const float4*)&x[((size_t)b * TSEQ + (t + 1)) * INDIM + 4 * tid];
        *(float4*)&g_comb[b * COMBP + 4 * tid] = xv;
    }
}

// ---------------- final out at t=255 ----------------
__global__ void __launch_bounds__(256) outfin_kernel(float* __restrict__ dout) {
    int b = blockIdx.x, j = threadIdx.x;
    float v = g_part[(0 * BATCH + b) * PARTW + j]
            + g_part[(1 * BATCH + b) * PARTW + j]
            + g_part[(2 * BATCH + b) * PARTW + j]
            + g_part[(3 * BATCH + b) * PARTW + j]
            + g_bias[j];
    dout[((size_t)b * TSEQ + (TSEQ - 1)) * DB + j] = sigm(v);
}

// ---------------- host ----------------
extern "C" void kernel_launch(void* const* d_in, const int* in_sizes, int n_in,
                              void* d_out, int out_size) {
    const float* x  = (const float*)d_in[0];
    const float* Wo = (const float*)d_in[1];
    const float* bo = (const float*)d_in[2];
    const float* Ws = (const float*)d_in[3];
    const float* bs = (const float*)d_in[4];
    const float* Wu = (const float*)d_in[5];
    const float* bu = (const float*)d_in[6];
    float* out = (float*)d_out;

    pack_kernel<<<(PARTW * COMBP + 255) / 256, 256>>>(Wo, bo, Ws, bs, Wu, bu);
    init_kernel<<<BATCH, 256>>>(x);
    for (int t = 0; t < TSEQ; t++) {
        gemm_kernel<<<dim3(NCB, KSPLIT), 256>>>();
        if (t < TSEQ - 1) update_kernel<<<256, 256>>>(x, out, t);
    }
    outfin_kernel<<<BATCH, 256>>>(out);
}